// round 4
// baseline (speedup 1.0000x reference)
#include <cuda_runtime.h>
#include <cuda_bf16.h>

// Problem constants (match reference)
#define B_  32
#define S_  128
#define I_  64
#define H_  1024
#define T_  4          // NUM_TIME_STEPS
#define DECAY      0.9f
#define THRESHOLD  1.0f
#define BETA       5.0f

#define TPB 128        // threads per block (h-tile)

// Fused LIF kernel, software-pipelined:
//   one thread owns one (b,h) lane; encoding column lives in 64 registers.
//   Double-buffered 32-wide load batches keep ~32 LDGs in flight per thread
//   at ALL times — including during the FMA reduction and the serial
//   4-step sigmoid/reset tail — so DRAM never goes idle.
//   x is read once (1 GiB): stream with __ldcs. Spikes stored with __stcs.
__global__ __launch_bounds__(TPB)
void lif_fused_kernel(const float* __restrict__ x,
                      const float* __restrict__ enc,
                      float* __restrict__ out)
{
    const int h = blockIdx.x * TPB + threadIdx.x;   // 0..1023
    const int b = blockIdx.y;                        // 0..31

    // Encoding column in registers (64 regs, reused across all 128 s-steps)
    float e[I_];
#pragma unroll
    for (int i = 0; i < I_; i++)
        e[i] = __ldg(enc + i * H_ + h);

    const float* xb = x + (size_t)b * S_ * I_ * H_ + h;
    float*       ob = out + (size_t)b * S_ * T_ * H_ + h;

    float v = 0.0f;

    float bufA[32], bufB[32];

    // Prologue: issue first half-batch of s=0
#pragma unroll
    for (int i = 0; i < 32; i++)
        bufA[i] = __ldcs(xb + i * H_);

    for (int s = 0; s < S_; s++) {
        const float* xs = xb + (size_t)s * (I_ * H_);

        // Issue second half of this step (stays in flight while we consume A)
#pragma unroll
        for (int i = 0; i < 32; i++)
            bufB[i] = __ldcs(xs + (32 + i) * H_);

        // Consume first half (i = 0..31), 4-way accumulator tree
        float d0 = 0.f, d1 = 0.f, d2 = 0.f, d3 = 0.f;
#pragma unroll
        for (int i = 0; i < 32; i += 4) {
            d0 = fmaf(e[i + 0], bufA[i + 0], d0);
            d1 = fmaf(e[i + 1], bufA[i + 1], d1);
            d2 = fmaf(e[i + 2], bufA[i + 2], d2);
            d3 = fmaf(e[i + 3], bufA[i + 3], d3);
        }

        // Issue first half of NEXT step — keeps loads in flight through the
        // B-consume and the serial LIF tail below.
        if (s + 1 < S_) {
            const float* xn = xs + (I_ * H_);
#pragma unroll
            for (int i = 0; i < 32; i++)
                bufA[i] = __ldcs(xn + i * H_);
        }

        // Consume second half (i = 32..63)
#pragma unroll
        for (int i = 0; i < 32; i += 4) {
            d0 = fmaf(e[32 + i + 0], bufB[i + 0], d0);
            d1 = fmaf(e[32 + i + 1], bufB[i + 1], d1);
            d2 = fmaf(e[32 + i + 2], bufB[i + 2], d2);
            d3 = fmaf(e[32 + i + 3], bufB[i + 3], d3);
        }
        const float drive = (d0 + d1) + (d2 + d3);

        // --- 4 LIF steps with the same drive (serial, hidden behind loads) ---
        float* os = ob + (size_t)s * T_ * H_;
#pragma unroll
        for (int t = 0; t < T_; t++) {
            v = DECAY * v + drive;
            // sigmoid(BETA*(v - THRESHOLD)) = 1 / (1 + exp(BETA*(THRESHOLD - v)))
            const float ex = __expf(BETA * (THRESHOLD - v));
            const float spike = __fdividef(1.0f, 1.0f + ex);
            v -= spike * THRESHOLD;
            __stcs(os + t * H_, spike);
        }
    }

    // v_final appended after the output sequence
    out[(size_t)B_ * S_ * T_ * H_ + (size_t)b * H_ + h] = v;
}

extern "C" void kernel_launch(void* const* d_in, const int* in_sizes, int n_in,
                              void* d_out, int out_size)
{
    const float* x   = (const float*)d_in[0];   // [32,128,64,1024] f32
    const float* enc = (const float*)d_in[1];   // [64,1024] f32
    float* out = (float*)d_out;                 // [32*512*1024 + 32*1024] f32

    dim3 grid(H_ / TPB, B_);   // (8, 32) = 256 blocks, all co-resident (1 wave)
    lif_fused_kernel<<<grid, TPB>>>(x, enc, out);
}

// round 5
// speedup vs baseline: 1.2416x; 1.2416x over previous
#include <cuda_runtime.h>
#include <cuda_bf16.h>

// Problem constants (match reference)
#define B_  32
#define S_  128
#define I_  64
#define H_  1024
#define T_  4          // NUM_TIME_STEPS
#define DECAY      0.9f
#define THRESHOLD  1.0f
#define BETA       5.0f

// 16 MB scratch for drive[b,s,h] (device global: no allocation, graph-safe)
__device__ float g_drive[(size_t)B_ * S_ * H_];

// ---------------------------------------------------------------------------
// Kernel 1: drive[b,s,h] = sum_i enc[i,h] * x[b,s,i,h]
// One thread per (b,s, h-float4). 1,048,576 threads -> high occupancy,
// DRAM saturation comes from warp count, not hand-tuned per-thread MLP.
// x is read once: stream (__ldcs). enc is tiny and hot in L1/L2 (__ldg).
// drive written with default policy so it stays resident in L2 for kernel 2.
// ---------------------------------------------------------------------------
#define K1_TPB 256

__global__ __launch_bounds__(K1_TPB)
void drive_kernel(const float* __restrict__ x,
                  const float* __restrict__ enc,
                  float* __restrict__ drive)
{
    const int idx = blockIdx.x * K1_TPB + threadIdx.x;  // 0 .. B*S*(H/4)-1
    const int h4  = idx & (H_ / 4 - 1);                 // float4 column, 0..255
    const int bs  = idx >> 8;                           // fused (b*S + s), 0..4095

    const float4* xp = reinterpret_cast<const float4*>(x + (size_t)bs * I_ * H_) + h4;
    const float4* ep = reinterpret_cast<const float4*>(enc) + h4;

    float4 a0 = make_float4(0.f, 0.f, 0.f, 0.f);
    float4 a1 = make_float4(0.f, 0.f, 0.f, 0.f);

#pragma unroll
    for (int i = 0; i < I_; i += 2) {
        const float4 xv0 = __ldcs(&xp[(i + 0) * (H_ / 4)]);
        const float4 xv1 = __ldcs(&xp[(i + 1) * (H_ / 4)]);
        const float4 ev0 = __ldg (&ep[(i + 0) * (H_ / 4)]);
        const float4 ev1 = __ldg (&ep[(i + 1) * (H_ / 4)]);
        a0.x = fmaf(ev0.x, xv0.x, a0.x);
        a0.y = fmaf(ev0.y, xv0.y, a0.y);
        a0.z = fmaf(ev0.z, xv0.z, a0.z);
        a0.w = fmaf(ev0.w, xv0.w, a0.w);
        a1.x = fmaf(ev1.x, xv1.x, a1.x);
        a1.y = fmaf(ev1.y, xv1.y, a1.y);
        a1.z = fmaf(ev1.z, xv1.z, a1.z);
        a1.w = fmaf(ev1.w, xv1.w, a1.w);
    }

    float4 r;
    r.x = a0.x + a1.x;
    r.y = a0.y + a1.y;
    r.z = a0.z + a1.z;
    r.w = a0.w + a1.w;
    reinterpret_cast<float4*>(drive)[idx] = r;   // L2-resident for kernel 2
}

// ---------------------------------------------------------------------------
// Kernel 2: LIF scan. One thread per (b,h) lane; 128 serial s-steps,
// 4 LIF sub-steps each. drive reads hit L2 (written by kernel 1).
// Critical path is the MUFU (EX2/RCP) dependency chain; drive prefetched
// one step ahead so loads never extend it.
// ---------------------------------------------------------------------------
#define K2_TPB 256

__global__ __launch_bounds__(K2_TPB)
void lif_scan_kernel(const float* __restrict__ drive,
                     float* __restrict__ out)
{
    const int idx = blockIdx.x * K2_TPB + threadIdx.x;  // 0 .. B*H-1
    const int h   = idx & (H_ - 1);
    const int b   = idx >> 10;

    const float* dp = drive + (size_t)b * S_ * H_ + h;
    float*       ob = out   + (size_t)b * S_ * T_ * H_ + h;

    float v   = 0.0f;
    float nxt = dp[0];

    for (int s = 0; s < S_; s++) {
        const float d = nxt;
        if (s + 1 < S_) nxt = dp[(size_t)(s + 1) * H_];  // prefetch next step

        float* os = ob + (size_t)s * T_ * H_;
#pragma unroll
        for (int t = 0; t < T_; t++) {
            v = DECAY * v + d;
            // sigmoid(BETA*(v - THRESHOLD)) = 1 / (1 + exp(BETA*(THRESHOLD - v)))
            const float ex    = __expf(BETA * (THRESHOLD - v));
            const float spike = __fdividef(1.0f, 1.0f + ex);
            v -= spike * THRESHOLD;
            __stcs(os + (size_t)t * H_, spike);
        }
    }

    // v_final appended after the output sequence
    out[(size_t)B_ * S_ * T_ * H_ + (size_t)b * H_ + h] = v;
}

// ---------------------------------------------------------------------------
extern "C" void kernel_launch(void* const* d_in, const int* in_sizes, int n_in,
                              void* d_out, int out_size)
{
    const float* x   = (const float*)d_in[0];   // [32,128,64,1024] f32
    const float* enc = (const float*)d_in[1];   // [64,1024] f32
    float* out = (float*)d_out;                 // [32*512*1024 + 32*1024] f32

    float* drive = nullptr;
    cudaGetSymbolAddress((void**)&drive, g_drive);   // host-side, graph-safe

    const int k1_blocks = (B_ * S_ * (H_ / 4)) / K1_TPB;  // 4096
    drive_kernel<<<k1_blocks, K1_TPB>>>(x, enc, drive);

    const int k2_blocks = (B_ * H_) / K2_TPB;             // 128
    lif_scan_kernel<<<k2_blocks, K2_TPB>>>(drive, out);
}

// round 7
// speedup vs baseline: 1.3176x; 1.0612x over previous
#include <cuda_runtime.h>
#include <cuda_bf16.h>

// Problem constants (match reference)
#define B_  32
#define S_  128
#define I_  64
#define H_  1024
#define T_  4          // NUM_TIME_STEPS
#define DECAY      0.9f
#define THRESHOLD  1.0f
#define BETA       5.0f

// Chunked-scan parameters.
// |d(v_next)/dv| <= 0.9 globally (0.9*(1 - 5*sig*(1-sig)) in [-0.225, 0.9]),
// so a cold start converges at 0.9/substep. WARMUP_S=40 s-steps = 160
// substeps: err_v <= ~100 * 0.9^160 ~ 5e-6 — negligible vs the 1e-3 bar.
// Chunks whose warm-up clamps to s=0 are EXACT (true initial state v=0).
#define NCHUNK    4
#define CHUNK_S   (S_ / NCHUNK)   // 32
#define WARMUP_S  40

// 16 MB scratch for drive[b,s,h] (device global: no allocation, graph-safe)
__device__ float g_drive[(size_t)B_ * S_ * H_];

// ---------------------------------------------------------------------------
// Kernel 1: drive[b,s,h] = sum_i enc[i,h] * x[b,s,i,h]
// One thread per (b,s, h-float4); occupancy-driven DRAM saturation.
// x streamed (__ldcs, read-once); enc hot in L1/L2; drive left L2-resident.
// ---------------------------------------------------------------------------
#define K1_TPB 256

__global__ __launch_bounds__(K1_TPB)
void drive_kernel(const float* __restrict__ x,
                  const float* __restrict__ enc,
                  float* __restrict__ drive)
{
    const int idx = blockIdx.x * K1_TPB + threadIdx.x;  // 0 .. B*S*(H/4)-1
    const int h4  = idx & (H_ / 4 - 1);                 // float4 column
    const int bs  = idx >> 8;                           // fused (b*S + s)

    const float4* xp = reinterpret_cast<const float4*>(x + (size_t)bs * I_ * H_) + h4;
    const float4* ep = reinterpret_cast<const float4*>(enc) + h4;

    float4 a0 = make_float4(0.f, 0.f, 0.f, 0.f);
    float4 a1 = make_float4(0.f, 0.f, 0.f, 0.f);

#pragma unroll
    for (int i = 0; i < I_; i += 2) {
        const float4 xv0 = __ldcs(&xp[(i + 0) * (H_ / 4)]);
        const float4 xv1 = __ldcs(&xp[(i + 1) * (H_ / 4)]);
        const float4 ev0 = __ldg (&ep[(i + 0) * (H_ / 4)]);
        const float4 ev1 = __ldg (&ep[(i + 1) * (H_ / 4)]);
        a0.x = fmaf(ev0.x, xv0.x, a0.x);
        a0.y = fmaf(ev0.y, xv0.y, a0.y);
        a0.z = fmaf(ev0.z, xv0.z, a0.z);
        a0.w = fmaf(ev0.w, xv0.w, a0.w);
        a1.x = fmaf(ev1.x, xv1.x, a1.x);
        a1.y = fmaf(ev1.y, xv1.y, a1.y);
        a1.z = fmaf(ev1.z, xv1.z, a1.z);
        a1.w = fmaf(ev1.w, xv1.w, a1.w);
    }

    float4 r;
    r.x = a0.x + a1.x;
    r.y = a0.y + a1.y;
    r.z = a0.z + a1.z;
    r.w = a0.w + a1.w;
    reinterpret_cast<float4*>(drive)[idx] = r;   // L2-resident for kernel 2
}

// ---------------------------------------------------------------------------
// Kernel 2: chunked LIF scan.
// One thread per (b, h, chunk). Chunk c owns s in [c*32, c*32+32), warm-starts
// up to WARMUP_S s-steps earlier with v=0 (clamped to s=0 -> exact for the
// early chunks). 131K threads -> ~28 warps/SM: the MUFU dependency chain,
// L2 drive loads, and spike stores all overlap across warps.
// ---------------------------------------------------------------------------
#define K2_TPB 256

__device__ __forceinline__ void lif_substep(float& v, float d, float& spike)
{
    v = fmaf(DECAY, v, d);
    // sigmoid(BETA*(v - THRESHOLD)) = 1 / (1 + exp(BETA*(THRESHOLD - v)))
    const float z  = fmaf(-BETA, v, BETA * THRESHOLD);
    const float ex = __expf(z);
    spike = __fdividef(1.0f, 1.0f + ex);
    v = fmaf(-spike, THRESHOLD, v);
}

__global__ __launch_bounds__(K2_TPB)
void lif_scan_kernel(const float* __restrict__ drive,
                     float* __restrict__ out)
{
    const int idx   = blockIdx.x * K2_TPB + threadIdx.x;  // 0 .. B*H*NCHUNK-1
    const int h     = idx & (H_ - 1);
    const int bc    = idx >> 10;
    const int b     = bc & (B_ - 1);
    const int chunk = bc >> 5;                            // 0..NCHUNK-1

    const int s_own   = chunk * CHUNK_S;                  // first owned s
    int s_start = s_own - WARMUP_S;
    if (s_start < 0) s_start = 0;                         // clamp (also: exact)

    const float* dp = drive + (size_t)b * S_ * H_ + h;
    float*       ob = out   + (size_t)b * S_ * T_ * H_ + h;

    float v = 0.0f;
    float spike;

    // Warm-up: run the recurrence, discard spikes.
    for (int s = s_start; s < s_own; s++) {
        const float d = __ldg(dp + (size_t)s * H_);
#pragma unroll
        for (int t = 0; t < T_; t++)
            lif_substep(v, d, spike);
    }

    // Owned range: store spikes.
    for (int s = s_own; s < s_own + CHUNK_S; s++) {
        const float d = __ldg(dp + (size_t)s * H_);
        float* os = ob + (size_t)s * T_ * H_;
#pragma unroll
        for (int t = 0; t < T_; t++) {
            lif_substep(v, d, spike);
            __stcs(os + (size_t)t * H_, spike);
        }
    }

    // Last chunk owns the final state.
    if (chunk == NCHUNK - 1)
        out[(size_t)B_ * S_ * T_ * H_ + (size_t)b * H_ + h] = v;
}

// ---------------------------------------------------------------------------
extern "C" void kernel_launch(void* const* d_in, const int* in_sizes, int n_in,
                              void* d_out, int out_size)
{
    const float* x   = (const float*)d_in[0];   // [32,128,64,1024] f32
    const float* enc = (const float*)d_in[1];   // [64,1024] f32
    float* out = (float*)d_out;                 // [32*512*1024 + 32*1024] f32

    float* drive = nullptr;
    cudaGetSymbolAddress((void**)&drive, g_drive);   // host-side, graph-safe

    const int k1_blocks = (B_ * S_ * (H_ / 4)) / K1_TPB;   // 4096
    drive_kernel<<<k1_blocks, K1_TPB>>>(x, enc, drive);

    const int k2_blocks = (B_ * H_ * NCHUNK) / K2_TPB;     // 512
    lif_scan_kernel<<<k2_blocks, K2_TPB>>>(drive, out);
}

// round 8
// speedup vs baseline: 1.3616x; 1.0334x over previous
#include <cuda_runtime.h>
#include <cuda_bf16.h>

// Problem constants (match reference)
#define B_  32
#define S_  128
#define I_  64
#define H_  1024
#define T_  4          // NUM_TIME_STEPS
#define DECAY      0.9f
#define THRESHOLD  1.0f
#define BETA       5.0f

// Chunked-scan parameters.
// |d(v_next)/dv| <= 0.9 globally, so a cold start converges at 0.9/substep.
// WARMUP_S=40 s-steps = 160 substeps: state error ~5e-6. Chunks whose
// warm-up clamps to s=0 are EXACT.
#define NCHUNK    4
#define CHUNK_S   (S_ / NCHUNK)   // 32
#define WARMUP_S  40

// 16 MB scratch for drive[b,s,h] (device global: no allocation, graph-safe)
__device__ float g_drive[(size_t)B_ * S_ * H_];

// ---------------------------------------------------------------------------
// Kernel 1: drive[b,s,h] = sum_i enc[i,h] * x[b,s,i,h]
// At ~86% of HBM spec (1.09 GB moved) — at the achievable roofline.
// ---------------------------------------------------------------------------
#define K1_TPB 256

__global__ __launch_bounds__(K1_TPB)
void drive_kernel(const float* __restrict__ x,
                  const float* __restrict__ enc,
                  float* __restrict__ drive)
{
    const int idx = blockIdx.x * K1_TPB + threadIdx.x;  // 0 .. B*S*(H/4)-1
    const int h4  = idx & (H_ / 4 - 1);                 // float4 column
    const int bs  = idx >> 8;                           // fused (b*S + s)

    const float4* xp = reinterpret_cast<const float4*>(x + (size_t)bs * I_ * H_) + h4;
    const float4* ep = reinterpret_cast<const float4*>(enc) + h4;

    float4 a0 = make_float4(0.f, 0.f, 0.f, 0.f);
    float4 a1 = make_float4(0.f, 0.f, 0.f, 0.f);

#pragma unroll
    for (int i = 0; i < I_; i += 2) {
        const float4 xv0 = __ldcs(&xp[(i + 0) * (H_ / 4)]);
        const float4 xv1 = __ldcs(&xp[(i + 1) * (H_ / 4)]);
        const float4 ev0 = __ldg (&ep[(i + 0) * (H_ / 4)]);
        const float4 ev1 = __ldg (&ep[(i + 1) * (H_ / 4)]);
        a0.x = fmaf(ev0.x, xv0.x, a0.x);
        a0.y = fmaf(ev0.y, xv0.y, a0.y);
        a0.z = fmaf(ev0.z, xv0.z, a0.z);
        a0.w = fmaf(ev0.w, xv0.w, a0.w);
        a1.x = fmaf(ev1.x, xv1.x, a1.x);
        a1.y = fmaf(ev1.y, xv1.y, a1.y);
        a1.z = fmaf(ev1.z, xv1.z, a1.z);
        a1.w = fmaf(ev1.w, xv1.w, a1.w);
    }

    float4 r;
    r.x = a0.x + a1.x;
    r.y = a0.y + a1.y;
    r.z = a0.z + a1.z;
    r.w = a0.w + a1.w;
    reinterpret_cast<float4*>(drive)[idx] = r;   // L2-resident for kernel 2
}

// ---------------------------------------------------------------------------
// Kernel 2: chunked LIF scan, tanh-based sigmoid.
//   sigmoid(z) = 0.5*tanh(z/2) + 0.5  ->  ONE MUFU per substep (tanh.approx),
//   vs 2 (EX2 + RCP) before: halves the MUFU-throughput floor and shortens
//   the serial dependency chain from ~52 to ~32 cycles per substep.
//   tanh.approx abs err ~1.3e-5 -> spike err ~6.5e-6, well under 1e-3.
// ---------------------------------------------------------------------------
#define K2_TPB 256

__device__ __forceinline__ float tanh_approx(float z)
{
    float r;
    asm("tanh.approx.f32 %0, %1;" : "=f"(r) : "f"(z));
    return r;
}

__device__ __forceinline__ void lif_substep(float& v, float d, float& spike)
{
    v = fmaf(DECAY, v, d);
    // sigmoid(BETA*(v-1)) = 0.5*tanh(0.5*BETA*(v-1)) + 0.5
    const float z = fmaf(0.5f * BETA, v, -0.5f * BETA * THRESHOLD);
    const float t = tanh_approx(z);
    spike = fmaf(0.5f, t, 0.5f);
    v -= spike * THRESHOLD;
}

__global__ __launch_bounds__(K2_TPB)
void lif_scan_kernel(const float* __restrict__ drive,
                     float* __restrict__ out)
{
    const int idx   = blockIdx.x * K2_TPB + threadIdx.x;  // 0 .. B*H*NCHUNK-1
    const int h     = idx & (H_ - 1);
    const int bc    = idx >> 10;
    const int b     = bc & (B_ - 1);
    const int chunk = bc >> 5;                            // 0..NCHUNK-1

    const int s_own = chunk * CHUNK_S;                    // first owned s
    int s_start = s_own - WARMUP_S;
    if (s_start < 0) s_start = 0;                         // clamp (exact)

    const float* dp = drive + (size_t)b * S_ * H_ + h;
    float*       ob = out   + (size_t)b * S_ * T_ * H_ + h;

    float v = 0.0f;
    float spike;

    // Warm-up: run the recurrence, discard spikes.
    for (int s = s_start; s < s_own; s++) {
        const float d = __ldg(dp + (size_t)s * H_);
#pragma unroll
        for (int t = 0; t < T_; t++)
            lif_substep(v, d, spike);
    }

    // Owned range: store spikes.
    for (int s = s_own; s < s_own + CHUNK_S; s++) {
        const float d = __ldg(dp + (size_t)s * H_);
        float* os = ob + (size_t)s * T_ * H_;
#pragma unroll
        for (int t = 0; t < T_; t++) {
            lif_substep(v, d, spike);
            __stcs(os + (size_t)t * H_, spike);
        }
    }

    // Last chunk owns the final state.
    if (chunk == NCHUNK - 1)
        out[(size_t)B_ * S_ * T_ * H_ + (size_t)b * H_ + h] = v;
}

// ---------------------------------------------------------------------------
extern "C" void kernel_launch(void* const* d_in, const int* in_sizes, int n_in,
                              void* d_out, int out_size)
{
    const float* x   = (const float*)d_in[0];   // [32,128,64,1024] f32
    const float* enc = (const float*)d_in[1];   // [64,1024] f32
    float* out = (float*)d_out;                 // [32*512*1024 + 32*1024] f32

    float* drive = nullptr;
    cudaGetSymbolAddress((void**)&drive, g_drive);   // host-side, graph-safe

    const int k1_blocks = (B_ * S_ * (H_ / 4)) / K1_TPB;   // 4096
    drive_kernel<<<k1_blocks, K1_TPB>>>(x, enc, drive);

    const int k2_blocks = (B_ * H_ * NCHUNK) / K2_TPB;     // 512
    lif_scan_kernel<<<k2_blocks, K2_TPB>>>(drive, out);
}